// round 10
// baseline (speedup 1.0000x reference)
#include <cuda_runtime.h>
#include <cuda_fp16.h>

// AdditiveAttention: out = softmax_k( sum_h w_v[h]*tanh(qp[q,h]+kp[k,h]) ) @ V
// B=4, Q=K=512, H=256, fp32 in/out.
// proj (split-f16 HMMA -> f16) ; vconv (V f32->f16) ;
// fused persistent: per 32-key tile {score tanh f16x2 -> exp (no-max softmax,
// scores bounded by sum|w_v|~13) -> PV f32 accum with f16 V}; divide at end.

#define Bv 4
#define Qv 512
#define Kv 512
#define Hv 256
#define MROWS 2048
#define NU 1024              // units = 2048 queries / 2
#define FG 456               // persistent grid: 3 blocks/SM x 152
#define NT 16                // 32-key tiles per unit

__device__ uint4 g_qph[MROWS * Hv / 8];     // projected q, f16
__device__ uint4 g_kph[MROWS * Hv / 8];     // projected k, f16
__device__ uint4 g_vh[Bv * Kv * Hv / 8];    // V converted to f16 (65536 uint4)

__device__ __forceinline__ __half2 tanh2_ap(__half2 x) {
    unsigned xi = *(unsigned*)&x, yi;
    asm("tanh.approx.f16x2 %0, %1;" : "=r"(yi) : "r"(xi));
    return *(__half2*)&yi;
}
__device__ __forceinline__ float ex2_ap(float x) {
    float y;
    asm("ex2.approx.f32 %0, %1;" : "=f"(y) : "f"(x));
    return y;
}
__device__ __forceinline__ void cp_async16(void* smem_dst, const void* gsrc) {
    unsigned s = (unsigned)__cvta_generic_to_shared(smem_dst);
    asm volatile("cp.async.cg.shared.global [%0], [%1], 16;\n" :: "r"(s), "l"(gsrc));
}
__device__ __forceinline__ void cp_commit() {
    asm volatile("cp.async.commit_group;\n");
}
__device__ __forceinline__ __half2 u2h(unsigned u) { return *(__half2*)&u; }

__device__ __forceinline__ void mma16816(float* d, const unsigned* a, const unsigned* b) {
    asm("mma.sync.aligned.m16n8k16.row.col.f32.f16.f16.f32 "
        "{%0,%1,%2,%3}, {%4,%5,%6,%7}, {%8,%9}, {%0,%1,%2,%3};"
        : "+f"(d[0]), "+f"(d[1]), "+f"(d[2]), "+f"(d[3])
        : "r"(a[0]), "r"(a[1]), "r"(a[2]), "r"(a[3]), "r"(b[0]), "r"(b[1]));
}

// ---------------------------------------------------------------------------
// Projection GEMM via HMMA (unchanged from R8, measured 11.2us).
// ---------------------------------------------------------------------------
#define PSTR 72

struct ProjSmem {
    __half Ahi[2][64 * PSTR];
    __half Alo[2][64 * PSTR];
    __half Whi[2][64 * PSTR];
    __half Wlo[2][64 * PSTR];
};

__global__ __launch_bounds__(128) void proj_kernel(
    const float* __restrict__ A0, const float* __restrict__ W0, __half* __restrict__ C0,
    const float* __restrict__ A1, const float* __restrict__ W1, __half* __restrict__ C1)
{
    const float* A; const float* W; __half* C;
    if (blockIdx.z == 0) { A = A0; W = W0; C = C0; }
    else                 { A = A1; W = W1; C = C1; }

    extern __shared__ char smraw[];
    ProjSmem* sm = (ProjSmem*)smraw;

    const int tid  = threadIdx.x;
    const int lane = tid & 31;
    const int wrp  = tid >> 5;
    const int bm = blockIdx.y * 64;
    const int bn = blockIdx.x * 64;
    const int warpM = (wrp >> 1) * 32;
    const int warpN = (wrp & 1) * 32;

    const float4* A4 = (const float4*)A;
    const float4* W4 = (const float4*)W;

    const int fr = tid >> 4;
    const int fc = tid & 15;

    float acc[2][4][4];
#pragma unroll
    for (int i = 0; i < 2; i++)
#pragma unroll
        for (int j = 0; j < 4; j++)
#pragma unroll
            for (int v = 0; v < 4; v++) acc[i][j][v] = 0.f;

    float4 abuf[8], wbuf[8];
#pragma unroll
    for (int j = 0; j < 8; j++) {
        abuf[j] = A4[(bm + fr + j * 8) * 64 + fc];
        wbuf[j] = W4[(bn + fr + j * 8) * 64 + fc];
    }

    int p = 0;
    for (int ch = 0; ch < 4; ch++) {
#pragma unroll
        for (int j = 0; j < 8; j++) {
            int r = fr + j * 8;
            float xs[4] = {abuf[j].x, abuf[j].y, abuf[j].z, abuf[j].w};
            float ys[4] = {wbuf[j].x, wbuf[j].y, wbuf[j].z, wbuf[j].w};
#pragma unroll
            for (int v = 0; v < 4; v++) {
                __half ah = __float2half_rn(xs[v]);
                __half al = __float2half_rn(xs[v] - __half2float(ah));
                sm->Ahi[p][r * PSTR + fc * 4 + v] = ah;
                sm->Alo[p][r * PSTR + fc * 4 + v] = al;
                __half wh = __float2half_rn(ys[v]);
                __half wl = __float2half_rn(ys[v] - __half2float(wh));
                sm->Whi[p][r * PSTR + fc * 4 + v] = wh;
                sm->Wlo[p][r * PSTR + fc * 4 + v] = wl;
            }
        }
        if (ch < 3) {
#pragma unroll
            for (int j = 0; j < 8; j++) {
                abuf[j] = A4[(bm + fr + j * 8) * 64 + (ch + 1) * 16 + fc];
                wbuf[j] = W4[(bn + fr + j * 8) * 64 + (ch + 1) * 16 + fc];
            }
        }
        __syncthreads();

        const __half* Ahi = sm->Ahi[p];
        const __half* Alo = sm->Alo[p];
        const __half* Whi = sm->Whi[p];
        const __half* Wlo = sm->Wlo[p];
        const int arow = warpM + (lane >> 2);
        const int kcol = (lane & 3) * 2;

#pragma unroll
        for (int ks = 0; ks < 4; ks++) {
            const int k0 = ks * 16 + kcol;
#pragma unroll
            for (int mb = 0; mb < 2; mb++) {
                const int r0 = arow + mb * 16;
                unsigned ah[4], al[4];
                ah[0] = *(const unsigned*)&Ahi[(r0    ) * PSTR + k0];
                ah[1] = *(const unsigned*)&Ahi[(r0 + 8) * PSTR + k0];
                ah[2] = *(const unsigned*)&Ahi[(r0    ) * PSTR + k0 + 8];
                ah[3] = *(const unsigned*)&Ahi[(r0 + 8) * PSTR + k0 + 8];
                al[0] = *(const unsigned*)&Alo[(r0    ) * PSTR + k0];
                al[1] = *(const unsigned*)&Alo[(r0 + 8) * PSTR + k0];
                al[2] = *(const unsigned*)&Alo[(r0    ) * PSTR + k0 + 8];
                al[3] = *(const unsigned*)&Alo[(r0 + 8) * PSTR + k0 + 8];
#pragma unroll
                for (int nb = 0; nb < 4; nb++) {
                    const int n0 = warpN + nb * 8 + (lane >> 2);
                    unsigned bh[2], bl[2];
                    bh[0] = *(const unsigned*)&Whi[n0 * PSTR + k0];
                    bh[1] = *(const unsigned*)&Whi[n0 * PSTR + k0 + 8];
                    bl[0] = *(const unsigned*)&Wlo[n0 * PSTR + k0];
                    bl[1] = *(const unsigned*)&Wlo[n0 * PSTR + k0 + 8];
                    mma16816(acc[mb][nb], ah, bh);
                    mma16816(acc[mb][nb], al, bh);
                    mma16816(acc[mb][nb], ah, bl);
                }
            }
        }
        __syncthreads();
        p ^= 1;
    }

    const int crow = warpM + (lane >> 2);
    const int ccol = warpN + (lane & 3) * 2;
#pragma unroll
    for (int mb = 0; mb < 2; mb++) {
#pragma unroll
        for (int nb = 0; nb < 4; nb++) {
            int r = bm + crow + mb * 16;
            int c = bn + ccol + nb * 8;
            __half2 h0 = __floats2half2_rn(acc[mb][nb][0], acc[mb][nb][1]);
            __half2 h1 = __floats2half2_rn(acc[mb][nb][2], acc[mb][nb][3]);
            *(unsigned*)&C[r * Hv + c]       = *(unsigned*)&h0;
            *(unsigned*)&C[(r + 8) * Hv + c] = *(unsigned*)&h1;
        }
    }
}

// ---------------------------------------------------------------------------
// V f32 -> f16 conversion: 524288 floats -> 65536 uint4. 256 blocks x 256 thr.
// ---------------------------------------------------------------------------
__global__ __launch_bounds__(256) void vconv_kernel(
    const float4* __restrict__ V, uint4* __restrict__ Vh)
{
    int idx = blockIdx.x * 256 + threadIdx.x;   // 0..65535
    float4 f0 = V[idx * 2];
    float4 f1 = V[idx * 2 + 1];
    __half2 h0 = __floats2half2_rn(f0.x, f0.y);
    __half2 h1 = __floats2half2_rn(f0.z, f0.w);
    __half2 h2 = __floats2half2_rn(f1.x, f1.y);
    __half2 h3 = __floats2half2_rn(f1.z, f1.w);
    uint4 u;
    u.x = *(unsigned*)&h0; u.y = *(unsigned*)&h1;
    u.z = *(unsigned*)&h2; u.w = *(unsigned*)&h3;
    Vh[idx] = u;
}

// ---------------------------------------------------------------------------
// Fused persistent kernel. 128 threads, grid 456, units of (2 queries x 512 keys),
// 16 tiles of 32 keys each. Per tile: score (tanh, MUFU) -> exp -> smem ps ->
// PV accumulate (FMA). No-max softmax; final divide by sum(exp).
// Thread roles: score: key = tid>>2, h-quarter = tid&3 (shfl-reduce groups of 4).
//               pv:    dims 2*tid, 2*tid+1, both queries.
// ---------------------------------------------------------------------------
struct FSmem {
    uint4 wvs[32];          // w_v f16, swizzled            (512B)
    float ps[2][32];        // exp(scores) current tile     (256B)
    float red[4][2];        // per-warp denom partials      (32B)
    float pad_[4];          // keep kb 16B-aligned          (16B)
    uint4 kb[2][1024];      // 2 x (32 keys x 256h f16)     (32KB)
    uint4 vb[2][1024];      // 2 x (32 keys x 256d f16)     (32KB)
};

// k smem swizzle: element (row r, col c[0..31]) -> r*32 + g(c,r)
__device__ __forceinline__ int kswz(int c, int r) {
    return (c & 24) | (((c ^ r) & 7) ^ ((c >> 2) & 6));
}
// wv swizzle: col c -> (c&24) | ((c&7) ^ ((c>>2)&6))
__device__ __forceinline__ int wswz(int c) {
    return (c & 24) | ((c & 7) ^ ((c >> 2) & 6));
}

__device__ __forceinline__ void issue_tile(
    FSmem* sm, int p, const uint4* kph, const uint4* vh,
    int b, int keybase, int tid)
{
    const uint4* ks = kph + (size_t)(b * Kv + keybase) * 32;
    const uint4* vs = vh + (size_t)(b * Kv + keybase) * 32;
#pragma unroll
    for (int j = 0; j < 8; j++) {
        int idx = j * 128 + tid;
        int r = idx >> 5, c = idx & 31;
        cp_async16(&sm->kb[p][r * 32 + kswz(c, r)], &ks[r * 32 + c]);
    }
#pragma unroll
    for (int j = 0; j < 8; j++) {
        int idx = j * 128 + tid;
        int r = idx >> 5, c = idx & 31;
        cp_async16(&sm->vb[p][r * 32 + c], &vs[r * 32 + c]);
    }
    cp_commit();
}

__global__ __launch_bounds__(128) void fused_kernel(
    const uint4* __restrict__ qp, const uint4* __restrict__ kp,
    const uint4* __restrict__ vh, const float* __restrict__ wv_g,
    float* __restrict__ out)
{
    extern __shared__ char smraw[];
    FSmem* sm = (FSmem*)smraw;

    const int tid  = threadIdx.x;
    const int lane = tid & 31;
    const int wrp  = tid >> 5;
    const int key  = tid >> 2;     // 0..31
    const int hq   = tid & 3;      // h-quarter

    const float LOG2E = 1.4426950408889634f;

    // w_v -> f16 smem (swizzled)
    if (tid < 32) {
        float4 f0 = *(const float4*)&wv_g[tid * 8];
        float4 f1 = *(const float4*)&wv_g[tid * 8 + 4];
        __half2 h0 = __floats2half2_rn(f0.x, f0.y);
        __half2 h1 = __floats2half2_rn(f0.z, f0.w);
        __half2 h2 = __floats2half2_rn(f1.x, f1.y);
        __half2 h3 = __floats2half2_rn(f1.z, f1.w);
        uint4 u;
        u.x = *(unsigned*)&h0; u.y = *(unsigned*)&h1;
        u.z = *(unsigned*)&h2; u.w = *(unsigned*)&h3;
        sm->wvs[wswz(tid)] = u;
    }

    int u = blockIdx.x;
    // load q regs for unit u: 2 rows, this thread's 64-h segment (8 uint4 each)
    uint4 q0[8], q1[8];
    {
        const uint4* qr = qp + (size_t)((u >> 8) * Qv + (u & 255) * 2) * 32 + hq * 8;
#pragma unroll
        for (int j = 0; j < 8; j++) { q0[j] = qr[j]; q1[j] = qr[32 + j]; }
    }
    issue_tile(sm, 0, kp, vh, u >> 8, 0, tid);

    int p = 0;
    while (true) {
        const int b = u >> 8;
        float den0 = 0.f, den1 = 0.f;
        float2 acc0 = make_float2(0.f, 0.f);
        float2 acc1 = make_float2(0.f, 0.f);

        for (int i = 0; i < NT; i++) {
            int nu_ = (i < NT - 1) ? u : (u + FG);
            int nk  = (i < NT - 1) ? (i + 1) * 32 : 0;
            if (nu_ < NU) {
                issue_tile(sm, p ^ 1, kp, vh, nu_ >> 8, nk, tid);
                asm volatile("cp.async.wait_group 1;\n");
            } else {
                asm volatile("cp.async.wait_group 0;\n");
            }
            __syncthreads();

            // ---- score: this thread's key, its 64-h quarter, both queries ----
            {
                const uint4* kbp = sm->kb[p];
                const int rb = key * 32;
                float s0 = 0.f, s1 = 0.f;
#pragma unroll
                for (int jj = 0; jj < 4; jj++) {
                    __half2 c0, c1;
#pragma unroll
                    for (int j2 = 0; j2 < 2; j2++) {
                        const int j = jj * 2 + j2;
                        const int col = hq * 8 + j;
                        uint4 ku = kbp[rb + kswz(col, key)];
                        uint4 wu = sm->wvs[wswz(col)];
                        uint4 qa = q0[j], qb = q1[j];
                        if (j2 == 0) {
                            c0 = __hmul2(tanh2_ap(__hadd2(u2h(qa.x), u2h(ku.x))), u2h(wu.x));
                            c1 = __hmul2(tanh2_ap(__hadd2(u2h(qb.x), u2h(ku.x))), u2h(wu.x));
                        } else {
                            c0 = __hfma2(tanh2_ap(__hadd2(u2h(qa.x), u2h(ku.x))), u2h(wu.x), c0);
                            c1 = __hfma2(tanh2_ap(__hadd2(u2h(qb.x), u2h(ku.x))), u2h(wu.x), c1);
                        }
                        c0 = __hfma2(tanh2_ap(__hadd2(u2h(qa.y), u2h(ku.y))), u2h(wu.y), c0);
                        c1 = __hfma2(tanh2_ap(__hadd2(u2h(qb.y), u2h(ku.y))), u2h(wu.y), c1);
                        c0 = __hfma2(tanh2_ap(__hadd2(u2h(qa.z), u2h(ku.z))), u2h(wu.z), c0);
                        c1 = __hfma2(tanh2_ap(__hadd2(u2h(qb.z), u2h(ku.z))), u2h(wu.z), c1);
                        c0 = __hfma2(tanh2_ap(__hadd2(u2h(qa.w), u2h(ku.w))), u2h(wu.w), c0);
                        c1 = __hfma2(tanh2_ap(__hadd2(u2h(qb.w), u2h(ku.w))), u2h(wu.w), c1);
                    }
                    float2 f0 = __half22float2(c0); s0 += f0.x + f0.y;
                    float2 f1 = __half22float2(c1); s1 += f1.x + f1.y;
                }
                s0 += __shfl_xor_sync(0xffffffffu, s0, 1);
                s0 += __shfl_xor_sync(0xffffffffu, s0, 2);
                s1 += __shfl_xor_sync(0xffffffffu, s1, 1);
                s1 += __shfl_xor_sync(0xffffffffu, s1, 2);
                float p0 = ex2_ap(s0 * LOG2E);
                float p1 = ex2_ap(s1 * LOG2E);
                den0 += 0.25f * p0;
                den1 += 0.25f * p1;
                if ((tid & 3) == 0) { sm->ps[0][key] = p0; sm->ps[1][key] = p1; }
            }
            __syncthreads();

            // ---- PV: dims 2*tid, 2*tid+1 (as one half2), 32 keys ----
            {
                const unsigned* vbp = (const unsigned*)sm->vb[p];
#pragma unroll 2
                for (int k4 = 0; k4 < 32; k4 += 4) {
                    float4 pp0 = *(const float4*)&sm->ps[0][k4];
                    float4 pp1 = *(const float4*)&sm->ps[1][k4];
                    float pa0[4] = {pp0.x, pp0.y, pp0.z, pp0.w};
                    float pa1[4] = {pp1.x, pp1.y, pp1.z, pp1.w};
#pragma unroll
                    for (int kk = 0; kk < 4; kk++) {
                        unsigned vu = vbp[(k4 + kk) * 128 + tid];
                        float2 vf = __half22float2(u2h(vu));
                        acc0.x = fmaf(pa0[kk], vf.x, acc0.x);
                        acc0.y = fmaf(pa0[kk], vf.y, acc0.y);
                        acc1.x = fmaf(pa1[kk], vf.x, acc1.x);
                        acc1.y = fmaf(pa1[kk], vf.y, acc1.y);
                    }
                }
            }
            __syncthreads();    // protect vb/ps before next prefetch/score
            p ^= 1;
        }

        // ---- epilogue: reduce denom, normalize, store ----
#pragma unroll
        for (int off = 16; off > 0; off >>= 1) {
            den0 += __shfl_xor_sync(0xffffffffu, den0, off);
            den1 += __shfl_xor_sync(0xffffffffu, den1, off);
        }
        if (lane == 0) { sm->red[wrp][0] = den0; sm->red[wrp][1] = den1; }
        __syncthreads();
        float d0 = sm->red[0][0] + sm->red[1][0] + sm->red[2][0] + sm->red[3][0];
        float d1 = sm->red[0][1] + sm->red[1][1] + sm->red[2][1] + sm->red[3][1];
        float i0 = __fdividef(1.f, d0);
        float i1 = __fdividef(1.f, d1);
        size_t row = (size_t)(b * Qv + (u & 255) * 2);
        float2 o0 = make_float2(acc0.x * i0, acc0.y * i0);
        float2 o1 = make_float2(acc1.x * i1, acc1.y * i1);
        *(float2*)&out[row * Hv + tid * 2]       = o0;
        *(float2*)&out[(row + 1) * Hv + tid * 2] = o1;

        u += FG;
        if (u >= NU) break;
        {
            const uint4* qr = qp + (size_t)((u >> 8) * Qv + (u & 255) * 2) * 32 + hq * 8;
#pragma unroll
            for (int j = 0; j < 8; j++) { q0[j] = qr[j]; q1[j] = qr[32 + j]; }
        }
        __syncthreads();   // red[] reuse guard
    }
}

extern "C" void kernel_launch(void* const* d_in, const int* in_sizes, int n_in,
                              void* d_out, int out_size)
{
    const float* queries = (const float*)d_in[0];
    const float* keys    = (const float*)d_in[1];
    const float* values  = (const float*)d_in[2];
    const float* W_q     = (const float*)d_in[3];
    const float* W_k     = (const float*)d_in[4];
    const float* w_v     = (const float*)d_in[5];
    float* out = (float*)d_out;

    uint4 *qph, *kph, *vhp;
    cudaGetSymbolAddress((void**)&qph, g_qph);
    cudaGetSymbolAddress((void**)&kph, g_kph);
    cudaGetSymbolAddress((void**)&vhp, g_vh);

    const int smP = (int)sizeof(ProjSmem);
    cudaFuncSetAttribute(proj_kernel, cudaFuncAttributeMaxDynamicSharedMemorySize, smP);
    proj_kernel<<<dim3(4, 32, 2), 128, smP>>>(queries, W_q, (__half*)qph,
                                              keys, W_k, (__half*)kph);

    vconv_kernel<<<256, 256>>>((const float4*)values, vhp);

    const int smF = (int)sizeof(FSmem);
    cudaFuncSetAttribute(fused_kernel, cudaFuncAttributeMaxDynamicSharedMemorySize, smF);
    fused_kernel<<<FG, 128, smF>>>(qph, kph, vhp, w_v, out);
}

// round 11
// speedup vs baseline: 1.6093x; 1.6093x over previous
#include <cuda_runtime.h>
#include <cuda_fp16.h>

// AdditiveAttention: out = softmax_k( sum_h w_v[h]*tanh(qp[q,h]+kp[k,h]) ) @ V
// B=4, Q=K=512, H=256, fp32 in/out.
// proj (split-f16 HMMA -> f16) -> vtrans (V f32 -> f16 transposed [dim][key])
// -> score (persistent f16x2 tanh, AT MUFU floor) -> softmax + PV via HMMA
// (P split hi/lo f16 = error-free, V f16).

#define Bv 4
#define Qv 512
#define Kv 512
#define Hv 256
#define MROWS 2048
#define SGRID 456
#define NUNITS 2048

__device__ uint4 g_qph[MROWS * Hv / 8];   // projected q, f16
__device__ uint4 g_kph[MROWS * Hv / 8];   // projected k, f16
__device__ float g_sc[Bv * Qv * Kv];      // scores, 4MB
__device__ uint4 g_vt[Bv * Hv * Kv / 8];  // V^T f16: [b][dim][key]

__device__ __forceinline__ __half2 tanh2_ap(__half2 x) {
    unsigned xi = *(unsigned*)&x, yi;
    asm("tanh.approx.f16x2 %0, %1;" : "=r"(yi) : "r"(xi));
    return *(__half2*)&yi;
}
__device__ __forceinline__ float ex2_ap(float x) {
    float y;
    asm("ex2.approx.f32 %0, %1;" : "=f"(y) : "f"(x));
    return y;
}
__device__ __forceinline__ void cp_async16(void* smem_dst, const void* gsrc) {
    unsigned s = (unsigned)__cvta_generic_to_shared(smem_dst);
    asm volatile("cp.async.cg.shared.global [%0], [%1], 16;\n" :: "r"(s), "l"(gsrc));
}
__device__ __forceinline__ void cp_commit() {
    asm volatile("cp.async.commit_group;\n");
}
__device__ __forceinline__ __half2 u2h(unsigned u) { return *(__half2*)&u; }

__device__ __forceinline__ void mma16816(float* d, const unsigned* a, const unsigned* b) {
    asm("mma.sync.aligned.m16n8k16.row.col.f32.f16.f16.f32 "
        "{%0,%1,%2,%3}, {%4,%5,%6,%7}, {%8,%9}, {%0,%1,%2,%3};"
        : "+f"(d[0]), "+f"(d[1]), "+f"(d[2]), "+f"(d[3])
        : "r"(a[0]), "r"(a[1]), "r"(a[2]), "r"(a[3]), "r"(b[0]), "r"(b[1]));
}

// ---------------------------------------------------------------------------
// Projection GEMM via HMMA (unchanged from R8, measured 11.2us).
// ---------------------------------------------------------------------------
#define PSTR 72

struct ProjSmem {
    __half Ahi[2][64 * PSTR];
    __half Alo[2][64 * PSTR];
    __half Whi[2][64 * PSTR];
    __half Wlo[2][64 * PSTR];
};

__global__ __launch_bounds__(128) void proj_kernel(
    const float* __restrict__ A0, const float* __restrict__ W0, __half* __restrict__ C0,
    const float* __restrict__ A1, const float* __restrict__ W1, __half* __restrict__ C1)
{
    const float* A; const float* W; __half* C;
    if (blockIdx.z == 0) { A = A0; W = W0; C = C0; }
    else                 { A = A1; W = W1; C = C1; }

    extern __shared__ char smraw[];
    ProjSmem* sm = (ProjSmem*)smraw;

    const int tid  = threadIdx.x;
    const int lane = tid & 31;
    const int wrp  = tid >> 5;
    const int bm = blockIdx.y * 64;
    const int bn = blockIdx.x * 64;
    const int warpM = (wrp >> 1) * 32;
    const int warpN = (wrp & 1) * 32;

    const float4* A4 = (const float4*)A;
    const float4* W4 = (const float4*)W;

    const int fr = tid >> 4;
    const int fc = tid & 15;

    float acc[2][4][4];
#pragma unroll
    for (int i = 0; i < 2; i++)
#pragma unroll
        for (int j = 0; j < 4; j++)
#pragma unroll
            for (int v = 0; v < 4; v++) acc[i][j][v] = 0.f;

    float4 abuf[8], wbuf[8];
#pragma unroll
    for (int j = 0; j < 8; j++) {
        abuf[j] = A4[(bm + fr + j * 8) * 64 + fc];
        wbuf[j] = W4[(bn + fr + j * 8) * 64 + fc];
    }

    int p = 0;
    for (int ch = 0; ch < 4; ch++) {
#pragma unroll
        for (int j = 0; j < 8; j++) {
            int r = fr + j * 8;
            float xs[4] = {abuf[j].x, abuf[j].y, abuf[j].z, abuf[j].w};
            float ys[4] = {wbuf[j].x, wbuf[j].y, wbuf[j].z, wbuf[j].w};
#pragma unroll
            for (int v = 0; v < 4; v++) {
                __half ah = __float2half_rn(xs[v]);
                __half al = __float2half_rn(xs[v] - __half2float(ah));
                sm->Ahi[p][r * PSTR + fc * 4 + v] = ah;
                sm->Alo[p][r * PSTR + fc * 4 + v] = al;
                __half wh = __float2half_rn(ys[v]);
                __half wl = __float2half_rn(ys[v] - __half2float(wh));
                sm->Whi[p][r * PSTR + fc * 4 + v] = wh;
                sm->Wlo[p][r * PSTR + fc * 4 + v] = wl;
            }
        }
        if (ch < 3) {
#pragma unroll
            for (int j = 0; j < 8; j++) {
                abuf[j] = A4[(bm + fr + j * 8) * 64 + (ch + 1) * 16 + fc];
                wbuf[j] = W4[(bn + fr + j * 8) * 64 + (ch + 1) * 16 + fc];
            }
        }
        __syncthreads();

        const __half* Ahi = sm->Ahi[p];
        const __half* Alo = sm->Alo[p];
        const __half* Whi = sm->Whi[p];
        const __half* Wlo = sm->Wlo[p];
        const int arow = warpM + (lane >> 2);
        const int kcol = (lane & 3) * 2;

#pragma unroll
        for (int ks = 0; ks < 4; ks++) {
            const int k0 = ks * 16 + kcol;
#pragma unroll
            for (int mb = 0; mb < 2; mb++) {
                const int r0 = arow + mb * 16;
                unsigned ah[4], al[4];
                ah[0] = *(const unsigned*)&Ahi[(r0    ) * PSTR + k0];
                ah[1] = *(const unsigned*)&Ahi[(r0 + 8) * PSTR + k0];
                ah[2] = *(const unsigned*)&Ahi[(r0    ) * PSTR + k0 + 8];
                ah[3] = *(const unsigned*)&Ahi[(r0 + 8) * PSTR + k0 + 8];
                al[0] = *(const unsigned*)&Alo[(r0    ) * PSTR + k0];
                al[1] = *(const unsigned*)&Alo[(r0 + 8) * PSTR + k0];
                al[2] = *(const unsigned*)&Alo[(r0    ) * PSTR + k0 + 8];
                al[3] = *(const unsigned*)&Alo[(r0 + 8) * PSTR + k0 + 8];
#pragma unroll
                for (int nb = 0; nb < 4; nb++) {
                    const int n0 = warpN + nb * 8 + (lane >> 2);
                    unsigned bh[2], bl[2];
                    bh[0] = *(const unsigned*)&Whi[n0 * PSTR + k0];
                    bh[1] = *(const unsigned*)&Whi[n0 * PSTR + k0 + 8];
                    bl[0] = *(const unsigned*)&Wlo[n0 * PSTR + k0];
                    bl[1] = *(const unsigned*)&Wlo[n0 * PSTR + k0 + 8];
                    mma16816(acc[mb][nb], ah, bh);
                    mma16816(acc[mb][nb], al, bh);
                    mma16816(acc[mb][nb], ah, bl);
                }
            }
        }
        __syncthreads();
        p ^= 1;
    }

    const int crow = warpM + (lane >> 2);
    const int ccol = warpN + (lane & 3) * 2;
#pragma unroll
    for (int mb = 0; mb < 2; mb++) {
#pragma unroll
        for (int nb = 0; nb < 4; nb++) {
            int r = bm + crow + mb * 16;
            int c = bn + ccol + nb * 8;
            __half2 h0 = __floats2half2_rn(acc[mb][nb][0], acc[mb][nb][1]);
            __half2 h1 = __floats2half2_rn(acc[mb][nb][2], acc[mb][nb][3]);
            *(unsigned*)&C[r * Hv + c]       = *(unsigned*)&h0;
            *(unsigned*)&C[(r + 8) * Hv + c] = *(unsigned*)&h1;
        }
    }
}

// ---------------------------------------------------------------------------
// V transpose + f32->f16: g_vt[b][dim][key]. Block = (b, 64-key, 64-dim) tile.
// grid 128 = 4b x 8kt x 4dt, 256 threads.
// ---------------------------------------------------------------------------
__global__ __launch_bounds__(256) void vtrans_kernel(
    const float4* __restrict__ V4, uint4* __restrict__ Vt)
{
    __shared__ __align__(16) __half ts[64 * 72];   // [d][k], stride 72 halves

    const int blk = blockIdx.x;
    const int b  = blk >> 5;
    const int kt = (blk >> 2) & 7;
    const int dt = blk & 3;
    const int tid = threadIdx.x;

#pragma unroll
    for (int j = 0; j < 4; j++) {
        int idx = j * 256 + tid;
        int k = idx >> 4, d4 = idx & 15;
        float4 v = V4[(size_t)(b * Kv + kt * 64 + k) * 64 + dt * 16 + d4];
        ts[(d4 * 4 + 0) * 72 + k] = __float2half_rn(v.x);
        ts[(d4 * 4 + 1) * 72 + k] = __float2half_rn(v.y);
        ts[(d4 * 4 + 2) * 72 + k] = __float2half_rn(v.z);
        ts[(d4 * 4 + 3) * 72 + k] = __float2half_rn(v.w);
    }
    __syncthreads();
#pragma unroll
    for (int j = 0; j < 2; j++) {
        int idx = j * 256 + tid;
        int d = idx >> 3, c = idx & 7;
        uint4 u = *(const uint4*)&ts[d * 72 + c * 8];
        Vt[(size_t)(b * Hv + dt * 64 + d) * 64 + kt * 8 + c] = u;
    }
}

// ---------------------------------------------------------------------------
// Score kernel (persistent, unchanged from R8/R5 best, ~60us = MUFU floor).
// ---------------------------------------------------------------------------
struct ScoreSmem {
    uint4 wvh[32];
    uint4 qsh[2][256];
    uint4 kbh[2][2048];
};

__device__ __forceinline__ void score_prefetch(
    ScoreSmem* sm, const uint4* qp, const uint4* kp, int u, int p, int tid)
{
    const int qt = u >> 3;
    const int kt = u & 7;
    const int b = qt >> 6;
    const int qbase = (qt & 63) * 8;
    const uint4* qsrc = qp + (size_t)(b * Qv + qbase) * 32;
    cp_async16(&sm->qsh[p][tid], &qsrc[tid]);
    const uint4* ksrc = kp + (size_t)(b * Kv + kt * 64) * 32;
#pragma unroll
    for (int j = 0; j < 8; j++) {
        int idx = j * 256 + tid;
        int r = idx >> 5, c = idx & 31;
        cp_async16(&sm->kbh[p][r * 32 + (c ^ (r & 31))], &ksrc[r * 32 + c]);
    }
}

__global__ __launch_bounds__(256) void score_kernel(
    const uint4* __restrict__ qp, const uint4* __restrict__ kp,
    const float* __restrict__ wv_g, float* __restrict__ scores)
{
    extern __shared__ char smraw[];
    ScoreSmem* sm = (ScoreSmem*)smraw;

    const int tid  = threadIdx.x;
    const int lane = tid & 31;
    const int w    = tid >> 5;

    if (tid < 32) {
        float4 f0 = *(const float4*)&wv_g[tid * 8];
        float4 f1 = *(const float4*)&wv_g[tid * 8 + 4];
        __half2 h0 = __floats2half2_rn(f0.x, f0.y);
        __half2 h1 = __floats2half2_rn(f0.z, f0.w);
        __half2 h2 = __floats2half2_rn(f1.x, f1.y);
        __half2 h3 = __floats2half2_rn(f1.z, f1.w);
        uint4 u;
        u.x = *(unsigned*)&h0; u.y = *(unsigned*)&h1;
        u.z = *(unsigned*)&h2; u.w = *(unsigned*)&h3;
        sm->wvh[tid] = u;
    }

    const int qg   = w >> 1;
    const int rowk = (w & 1) * 32 + lane;
    const int q0   = qg * 2;

    int u = blockIdx.x;
    score_prefetch(sm, qp, kp, u, 0, tid);
    cp_commit();
    int p = 0;

    while (u < NUNITS) {
        int un = u + SGRID;
        if (un < NUNITS) {
            score_prefetch(sm, qp, kp, un, p ^ 1, tid);
            cp_commit();
            asm volatile("cp.async.wait_group 1;\n");
        } else {
            asm volatile("cp.async.wait_group 0;\n");
        }
        __syncthreads();

        const uint4* kb = sm->kbh[p];
        const uint4* qs = sm->qsh[p];
        float a00 = 0.f, a01 = 0.f, a10 = 0.f, a11 = 0.f;
#pragma unroll 4
        for (int h16 = 0; h16 < 16; h16++) {
            const int hA = 2 * h16, hB = 2 * h16 + 1;
            uint4 kuA = kb[rowk * 32 + (hA ^ lane)];
            uint4 kuB = kb[rowk * 32 + (hB ^ lane)];
            uint4 quA0 = qs[q0 * 32 + hA];
            uint4 quB0 = qs[q0 * 32 + hB];
            uint4 quA1 = qs[q0 * 32 + 32 + hA];
            uint4 quB1 = qs[q0 * 32 + 32 + hB];
            uint4 wuA = sm->wvh[hA];
            uint4 wuB = sm->wvh[hB];
            __half2 kA0 = u2h(kuA.x), kA1 = u2h(kuA.y), kA2 = u2h(kuA.z), kA3 = u2h(kuA.w);
            __half2 kB0 = u2h(kuB.x), kB1 = u2h(kuB.y), kB2 = u2h(kuB.z), kB3 = u2h(kuB.w);
            __half2 wA0 = u2h(wuA.x), wA1 = u2h(wuA.y), wA2 = u2h(wuA.z), wA3 = u2h(wuA.w);
            __half2 wB0 = u2h(wuB.x), wB1 = u2h(wuB.y), wB2 = u2h(wuB.z), wB3 = u2h(wuB.w);
            __half2 s0;
            s0 = __hmul2(tanh2_ap(__hadd2(u2h(quA0.x), kA0)), wA0);
            s0 = __hfma2(tanh2_ap(__hadd2(u2h(quA0.y), kA1)), wA1, s0);
            s0 = __hfma2(tanh2_ap(__hadd2(u2h(quA0.z), kA2)), wA2, s0);
            s0 = __hfma2(tanh2_ap(__hadd2(u2h(quA0.w), kA3)), wA3, s0);
            s0 = __hfma2(tanh2_ap(__hadd2(u2h(quB0.x), kB0)), wB0, s0);
            s0 = __hfma2(tanh2_ap(__hadd2(u2h(quB0.y), kB1)), wB1, s0);
            s0 = __hfma2(tanh2_ap(__hadd2(u2h(quB0.z), kB2)), wB2, s0);
            s0 = __hfma2(tanh2_ap(__hadd2(u2h(quB0.w), kB3)), wB3, s0);
            float2 f0 = __half22float2(s0);
            a00 += f0.x; a01 += f0.y;
            __half2 s1;
            s1 = __hmul2(tanh2_ap(__hadd2(u2h(quA1.x), kA0)), wA0);
            s1 = __hfma2(tanh2_ap(__hadd2(u2h(quA1.y), kA1)), wA1, s1);
            s1 = __hfma2(tanh2_ap(__hadd2(u2h(quA1.z), kA2)), wA2, s1);
            s1 = __hfma2(tanh2_ap(__hadd2(u2h(quA1.w), kA3)), wA3, s1);
            s1 = __hfma2(tanh2_ap(__hadd2(u2h(quB1.x), kB0)), wB0, s1);
            s1 = __hfma2(tanh2_ap(__hadd2(u2h(quB1.y), kB1)), wB1, s1);
            s1 = __hfma2(tanh2_ap(__hadd2(u2h(quB1.z), kB2)), wB2, s1);
            s1 = __hfma2(tanh2_ap(__hadd2(u2h(quB1.w), kB3)), wB3, s1);
            float2 f1 = __half22float2(s1);
            a10 += f1.x; a11 += f1.y;
        }
        {
            const int qt = u >> 3;
            const int kt = u & 7;
            const int b = qt >> 6;
            const int qbase = (qt & 63) * 8;
            const int key = kt * 64 + rowk;
            scores[(size_t)(b * Qv + qbase + q0) * Kv + key]     = a00 + a01;
            scores[(size_t)(b * Qv + qbase + q0 + 1) * Kv + key] = a10 + a11;
        }
        __syncthreads();
        u = un; p ^= 1;
    }
}

// ---------------------------------------------------------------------------
// Softmax + PV via HMMA. Block = 16 queries, 256 threads (8 warps), grid 128.
// Softmax: warp w -> queries 2w, 2w+1; probs split hi/lo f16 into smem.
// PV: out[16,256] = Phi*Vt + Plo*Vt, warp w -> 32-dim slice, V^T tiles of 32
// keys double-buffered via cp.async.
// smem: Phi[16][520] 16.6KB | Plo 16.6KB | Vt[2][256][56] 57.3KB = 90.6KB
// ---------------------------------------------------------------------------
#define PQ 16
#define PPS 520          // P row stride (halves)
#define VTS 56           // Vt smem row stride (halves); 112B -> conflict-free

struct PvSmem {
    __half Phi[PQ * PPS];
    __half Plo[PQ * PPS];
    __half Vt[2][Hv * VTS];
};

__device__ __forceinline__ void pv_vtile(
    PvSmem* sm, int p, const uint4* vt, int b, int kt, int tid)
{
#pragma unroll
    for (int j = 0; j < 4; j++) {
        int idx = j * 256 + tid;
        int d = idx >> 2, c = idx & 3;
        cp_async16(&sm->Vt[p][d * VTS + c * 8],
                   &vt[(size_t)(b * Hv + d) * 64 + kt * 4 + c]);
    }
    cp_commit();
}

__global__ __launch_bounds__(256) void softmax_pv_kernel(
    const float* __restrict__ scores, const uint4* __restrict__ vt,
    float* __restrict__ out)
{
    extern __shared__ char smraw[];
    PvSmem* sm = (PvSmem*)smraw;

    const int tid  = threadIdx.x;
    const int lane = tid & 31;
    const int w    = tid >> 5;
    const int b     = blockIdx.x >> 5;
    const int qbase = (blockIdx.x & 31) * PQ;

    pv_vtile(sm, 0, vt, b, 0, tid);

    // ---- softmax: warp w -> queries 2w, 2w+1 ----
    const float LOG2E = 1.4426950408889634f;
#pragma unroll
    for (int qq = 0; qq < 2; qq++) {
        const int q = 2 * w + qq;
        const float* src = &scores[(size_t)(b * Qv + qbase + q) * Kv];
        float4 xv[4];
        float mx = -1e30f;
#pragma unroll
        for (int j = 0; j < 4; j++) {
            xv[j] = *(const float4*)&src[j * 128 + lane * 4];
            mx = fmaxf(mx, fmaxf(fmaxf(xv[j].x, xv[j].y), fmaxf(xv[j].z, xv[j].w)));
        }
#pragma unroll
        for (int off = 16; off > 0; off >>= 1)
            mx = fmaxf(mx, __shfl_xor_sync(0xffffffffu, mx, off));
        float s = 0.f;
#pragma unroll
        for (int j = 0; j < 4; j++) {
            xv[j].x = ex2_ap((xv[j].x - mx) * LOG2E);
            xv[j].y = ex2_ap((xv[j].y - mx) * LOG2E);
            xv[j].z = ex2_ap((xv[j].z - mx) * LOG2E);
            xv[j].w = ex2_ap((xv[j].w - mx) * LOG2E);
            s += xv[j].x + xv[j].y + xv[j].z + xv[j].w;
        }
#pragma unroll
        for (int off = 16; off > 0; off >>= 1)
            s += __shfl_xor_sync(0xffffffffu, s, off);
        float inv = __fdividef(1.f, s);
#pragma unroll
        for (int j = 0; j < 4; j++) {
            float pv4[4] = {xv[j].x * inv, xv[j].y * inv, xv[j].z * inv, xv[j].w * inv};
            __half hi[4]; __half lo[4];
#pragma unroll
            for (int i = 0; i < 4; i++) {
                hi[i] = __float2half_rn(pv4[i]);
                lo[i] = __float2half_rn(pv4[i] - __half2float(hi[i]));
            }
            const int off4 = q * PPS + j * 128 + lane * 4;
            *(uint2*)&sm->Phi[off4] = *(uint2*)hi;
            *(uint2*)&sm->Plo[off4] = *(uint2*)lo;
        }
    }
    __syncthreads();

    // ---- PV MMA: warp w -> dims w*32..+32, all 16 queries ----
    const int warpN = w * 32;
    const int kcol  = (lane & 3) * 2;
    const int r0    = lane >> 2;

    float acc[4][4];
#pragma unroll
    for (int nb = 0; nb < 4; nb++)
#pragma unroll
        for (int v = 0; v < 4; v++) acc[nb][v] = 0.f;

    int p = 0;
    for (int kt = 0; kt < 16; kt++) {
        if (kt < 15) {
            pv_vtile(sm, p ^ 1, vt, b, kt + 1, tid);
            asm volatile("cp.async.wait_group 1;\n");
        } else {
            asm volatile("cp.async.wait_group 0;\n");
        }
        __syncthreads();

        const __half* vts = sm->Vt[p];
#pragma unroll
        for (int ks = 0; ks < 2; ks++) {
            const int ka = kt * 32 + ks * 16 + kcol;   // P column
            unsigned ah[4], al[4];
            ah[0] = *(const unsigned*)&sm->Phi[(r0    ) * PPS + ka];
            ah[1] = *(const unsigned*)&sm->Phi[(r0 + 8) * PPS + ka];
            ah[2] = *(const unsigned*)&sm->Phi[(r0    ) * PPS + ka + 8];
            ah[3] = *(const unsigned*)&sm->Phi[(r0 + 8) * PPS + ka + 8];
            al[0] = *(const unsigned*)&sm->Plo[(r0    ) * PPS + ka];
            al[1] = *(const unsigned*)&sm->Plo[(r0 + 8) * PPS + ka];
            al[2] = *(const unsigned*)&sm->Plo[(r0    ) * PPS + ka + 8];
            al[3] = *(const unsigned*)&sm->Plo[(r0 + 8) * PPS + ka + 8];
            const int kb = ks * 16 + kcol;             // Vt smem column
#pragma unroll
            for (int nb = 0; nb < 4; nb++) {
                const int n0 = warpN + nb * 8 + r0;
                unsigned bh[2];
                bh[0] = *(const unsigned*)&vts[n0 * VTS + kb];
                bh[1] = *(const unsigned*)&vts[n0 * VTS + kb + 8];
                mma16816(acc[nb], ah, bh);
                mma16816(acc[nb], al, bh);
            }
        }
        __syncthreads();
        p ^= 1;
    }

    // ---- store ----
    const int col = warpN + (lane & 3) * 2;
#pragma unroll
    for (int nb = 0; nb < 4; nb++) {
        size_t base0 = (size_t)(b * Qv + qbase + r0) * Hv + col + nb * 8;
        size_t base1 = (size_t)(b * Qv + qbase + r0 + 8) * Hv + col + nb * 8;
        *(float2*)&out[base0] = make_float2(acc[nb][0], acc[nb][1]);
        *(float2*)&out[base1] = make_float2(acc[nb][2], acc[nb][3]);
    }
}

extern "C" void kernel_launch(void* const* d_in, const int* in_sizes, int n_in,
                              void* d_out, int out_size)
{
    const float* queries = (const float*)d_in[0];
    const float* keys    = (const float*)d_in[1];
    const float* values  = (const float*)d_in[2];
    const float* W_q     = (const float*)d_in[3];
    const float* W_k     = (const float*)d_in[4];
    const float* w_v     = (const float*)d_in[5];
    float* out = (float*)d_out;

    uint4 *qph, *kph, *vtp; float* sc;
    cudaGetSymbolAddress((void**)&qph, g_qph);
    cudaGetSymbolAddress((void**)&kph, g_kph);
    cudaGetSymbolAddress((void**)&vtp, g_vt);
    cudaGetSymbolAddress((void**)&sc, g_sc);

    const int smP = (int)sizeof(ProjSmem);
    cudaFuncSetAttribute(proj_kernel, cudaFuncAttributeMaxDynamicSharedMemorySize, smP);
    proj_kernel<<<dim3(4, 32, 2), 128, smP>>>(queries, W_q, (__half*)qph,
                                              keys, W_k, (__half*)kph);

    vtrans_kernel<<<128, 256>>>((const float4*)values, vtp);

    const int smA = (int)sizeof(ScoreSmem);
    cudaFuncSetAttribute(score_kernel, cudaFuncAttributeMaxDynamicSharedMemorySize, smA);
    score_kernel<<<SGRID, 256, smA>>>(qph, kph, w_v, sc);

    const int smB = (int)sizeof(PvSmem);
    cudaFuncSetAttribute(softmax_pv_kernel, cudaFuncAttributeMaxDynamicSharedMemorySize, smB);
    softmax_pv_kernel<<<128, 256, smB>>>(sc, vtp, out);
}

// round 12
// speedup vs baseline: 1.6487x; 1.0245x over previous
#include <cuda_runtime.h>
#include <cuda_fp16.h>

// AdditiveAttention: out = softmax_k( sum_h w_v[h]*tanh(qp[q,h]+kp[k,h]) ) @ V
// B=4, Q=K=512, H=256, fp32 in/out.
// proj (split-f16 HMMA -> f16) -> vtrans (V f32 -> f16 transposed [dim][key])
// -> score (persistent f16x2 tanh, AT MUFU floor) -> softmax + PV via HMMA
// (P split hi/lo f16 = error-free; warp-private V tiles -> barrier-free mainloop).

#define Bv 4
#define Qv 512
#define Kv 512
#define Hv 256
#define MROWS 2048
#define SGRID 456
#define NUNITS 2048

__device__ uint4 g_qph[MROWS * Hv / 8];   // projected q, f16
__device__ uint4 g_kph[MROWS * Hv / 8];   // projected k, f16
__device__ float g_sc[Bv * Qv * Kv];      // scores, 4MB
__device__ uint4 g_vt[Bv * Hv * Kv / 8];  // V^T f16: [b][dim][key]

__device__ __forceinline__ __half2 tanh2_ap(__half2 x) {
    unsigned xi = *(unsigned*)&x, yi;
    asm("tanh.approx.f16x2 %0, %1;" : "=r"(yi) : "r"(xi));
    return *(__half2*)&yi;
}
__device__ __forceinline__ float ex2_ap(float x) {
    float y;
    asm("ex2.approx.f32 %0, %1;" : "=f"(y) : "f"(x));
    return y;
}
__device__ __forceinline__ void cp_async16(void* smem_dst, const void* gsrc) {
    unsigned s = (unsigned)__cvta_generic_to_shared(smem_dst);
    asm volatile("cp.async.cg.shared.global [%0], [%1], 16;\n" :: "r"(s), "l"(gsrc));
}
__device__ __forceinline__ void cp_commit() {
    asm volatile("cp.async.commit_group;\n");
}
__device__ __forceinline__ __half2 u2h(unsigned u) { return *(__half2*)&u; }

__device__ __forceinline__ void mma16816(float* d, const unsigned* a, const unsigned* b) {
    asm("mma.sync.aligned.m16n8k16.row.col.f32.f16.f16.f32 "
        "{%0,%1,%2,%3}, {%4,%5,%6,%7}, {%8,%9}, {%0,%1,%2,%3};"
        : "+f"(d[0]), "+f"(d[1]), "+f"(d[2]), "+f"(d[3])
        : "r"(a[0]), "r"(a[1]), "r"(a[2]), "r"(a[3]), "r"(b[0]), "r"(b[1]));
}

// ---------------------------------------------------------------------------
// Projection GEMM via HMMA (unchanged from R8, measured 11.2us).
// ---------------------------------------------------------------------------
#define PSTR 72

struct ProjSmem {
    __half Ahi[2][64 * PSTR];
    __half Alo[2][64 * PSTR];
    __half Whi[2][64 * PSTR];
    __half Wlo[2][64 * PSTR];
};

__global__ __launch_bounds__(128) void proj_kernel(
    const float* __restrict__ A0, const float* __restrict__ W0, __half* __restrict__ C0,
    const float* __restrict__ A1, const float* __restrict__ W1, __half* __restrict__ C1)
{
    const float* A; const float* W; __half* C;
    if (blockIdx.z == 0) { A = A0; W = W0; C = C0; }
    else                 { A = A1; W = W1; C = C1; }

    extern __shared__ char smraw[];
    ProjSmem* sm = (ProjSmem*)smraw;

    const int tid  = threadIdx.x;
    const int lane = tid & 31;
    const int wrp  = tid >> 5;
    const int bm = blockIdx.y * 64;
    const int bn = blockIdx.x * 64;
    const int warpM = (wrp >> 1) * 32;
    const int warpN = (wrp & 1) * 32;

    const float4* A4 = (const float4*)A;
    const float4* W4 = (const float4*)W;

    const int fr = tid >> 4;
    const int fc = tid & 15;

    float acc[2][4][4];
#pragma unroll
    for (int i = 0; i < 2; i++)
#pragma unroll
        for (int j = 0; j < 4; j++)
#pragma unroll
            for (int v = 0; v < 4; v++) acc[i][j][v] = 0.f;

    float4 abuf[8], wbuf[8];
#pragma unroll
    for (int j = 0; j < 8; j++) {
        abuf[j] = A4[(bm + fr + j * 8) * 64 + fc];
        wbuf[j] = W4[(bn + fr + j * 8) * 64 + fc];
    }

    int p = 0;
    for (int ch = 0; ch < 4; ch++) {
#pragma unroll
        for (int j = 0; j < 8; j++) {
            int r = fr + j * 8;
            float xs[4] = {abuf[j].x, abuf[j].y, abuf[j].z, abuf[j].w};
            float ys[4] = {wbuf[j].x, wbuf[j].y, wbuf[j].z, wbuf[j].w};
#pragma unroll
            for (int v = 0; v < 4; v++) {
                __half ah = __float2half_rn(xs[v]);
                __half al = __float2half_rn(xs[v] - __half2float(ah));
                sm->Ahi[p][r * PSTR + fc * 4 + v] = ah;
                sm->Alo[p][r * PSTR + fc * 4 + v] = al;
                __half wh = __float2half_rn(ys[v]);
                __half wl = __float2half_rn(ys[v] - __half2float(wh));
                sm->Whi[p][r * PSTR + fc * 4 + v] = wh;
                sm->Wlo[p][r * PSTR + fc * 4 + v] = wl;
            }
        }
        if (ch < 3) {
#pragma unroll
            for (int j = 0; j < 8; j++) {
                abuf[j] = A4[(bm + fr + j * 8) * 64 + (ch + 1) * 16 + fc];
                wbuf[j] = W4[(bn + fr + j * 8) * 64 + (ch + 1) * 16 + fc];
            }
        }
        __syncthreads();

        const __half* Ahi = sm->Ahi[p];
        const __half* Alo = sm->Alo[p];
        const __half* Whi = sm->Whi[p];
        const __half* Wlo = sm->Wlo[p];
        const int arow = warpM + (lane >> 2);
        const int kcol = (lane & 3) * 2;

#pragma unroll
        for (int ks = 0; ks < 4; ks++) {
            const int k0 = ks * 16 + kcol;
#pragma unroll
            for (int mb = 0; mb < 2; mb++) {
                const int r0 = arow + mb * 16;
                unsigned ah[4], al[4];
                ah[0] = *(const unsigned*)&Ahi[(r0    ) * PSTR + k0];
                ah[1] = *(const unsigned*)&Ahi[(r0 + 8) * PSTR + k0];
                ah[2] = *(const unsigned*)&Ahi[(r0    ) * PSTR + k0 + 8];
                ah[3] = *(const unsigned*)&Ahi[(r0 + 8) * PSTR + k0 + 8];
                al[0] = *(const unsigned*)&Alo[(r0    ) * PSTR + k0];
                al[1] = *(const unsigned*)&Alo[(r0 + 8) * PSTR + k0];
                al[2] = *(const unsigned*)&Alo[(r0    ) * PSTR + k0 + 8];
                al[3] = *(const unsigned*)&Alo[(r0 + 8) * PSTR + k0 + 8];
#pragma unroll
                for (int nb = 0; nb < 4; nb++) {
                    const int n0 = warpN + nb * 8 + (lane >> 2);
                    unsigned bh[2], bl[2];
                    bh[0] = *(const unsigned*)&Whi[n0 * PSTR + k0];
                    bh[1] = *(const unsigned*)&Whi[n0 * PSTR + k0 + 8];
                    bl[0] = *(const unsigned*)&Wlo[n0 * PSTR + k0];
                    bl[1] = *(const unsigned*)&Wlo[n0 * PSTR + k0 + 8];
                    mma16816(acc[mb][nb], ah, bh);
                    mma16816(acc[mb][nb], al, bh);
                    mma16816(acc[mb][nb], ah, bl);
                }
            }
        }
        __syncthreads();
        p ^= 1;
    }

    const int crow = warpM + (lane >> 2);
    const int ccol = warpN + (lane & 3) * 2;
#pragma unroll
    for (int mb = 0; mb < 2; mb++) {
#pragma unroll
        for (int nb = 0; nb < 4; nb++) {
            int r = bm + crow + mb * 16;
            int c = bn + ccol + nb * 8;
            __half2 h0 = __floats2half2_rn(acc[mb][nb][0], acc[mb][nb][1]);
            __half2 h1 = __floats2half2_rn(acc[mb][nb][2], acc[mb][nb][3]);
            *(unsigned*)&C[r * Hv + c]       = *(unsigned*)&h0;
            *(unsigned*)&C[(r + 8) * Hv + c] = *(unsigned*)&h1;
        }
    }
}

// ---------------------------------------------------------------------------
// V transpose + f32->f16: g_vt[b][dim][key]. grid 128 = 4b x 8kt x 4dt.
// ---------------------------------------------------------------------------
__global__ __launch_bounds__(256) void vtrans_kernel(
    const float4* __restrict__ V4, uint4* __restrict__ Vt)
{
    __shared__ __align__(16) __half ts[64 * 72];   // [d][k], stride 72 halves

    const int blk = blockIdx.x;
    const int b  = blk >> 5;
    const int kt = (blk >> 2) & 7;
    const int dt = blk & 3;
    const int tid = threadIdx.x;

#pragma unroll
    for (int j = 0; j < 4; j++) {
        int idx = j * 256 + tid;
        int k = idx >> 4, d4 = idx & 15;
        float4 v = V4[(size_t)(b * Kv + kt * 64 + k) * 64 + dt * 16 + d4];
        ts[(d4 * 4 + 0) * 72 + k] = __float2half_rn(v.x);
        ts[(d4 * 4 + 1) * 72 + k] = __float2half_rn(v.y);
        ts[(d4 * 4 + 2) * 72 + k] = __float2half_rn(v.z);
        ts[(d4 * 4 + 3) * 72 + k] = __float2half_rn(v.w);
    }
    __syncthreads();
#pragma unroll
    for (int j = 0; j < 2; j++) {
        int idx = j * 256 + tid;
        int d = idx >> 3, c = idx & 7;
        uint4 u = *(const uint4*)&ts[d * 72 + c * 8];
        Vt[(size_t)(b * Hv + dt * 64 + d) * 64 + kt * 8 + c] = u;
    }
}

// ---------------------------------------------------------------------------
// Score kernel (persistent, unchanged, ~56us = MUFU floor).
// ---------------------------------------------------------------------------
struct ScoreSmem {
    uint4 wvh[32];
    uint4 qsh[2][256];
    uint4 kbh[2][2048];
};

__device__ __forceinline__ void score_prefetch(
    ScoreSmem* sm, const uint4* qp, const uint4* kp, int u, int p, int tid)
{
    const int qt = u >> 3;
    const int kt = u & 7;
    const int b = qt >> 6;
    const int qbase = (qt & 63) * 8;
    const uint4* qsrc = qp + (size_t)(b * Qv + qbase) * 32;
    cp_async16(&sm->qsh[p][tid], &qsrc[tid]);
    const uint4* ksrc = kp + (size_t)(b * Kv + kt * 64) * 32;
#pragma unroll
    for (int j = 0; j < 8; j++) {
        int idx = j * 256 + tid;
        int r = idx >> 5, c = idx & 31;
        cp_async16(&sm->kbh[p][r * 32 + (c ^ (r & 31))], &ksrc[r * 32 + c]);
    }
}

__global__ __launch_bounds__(256) void score_kernel(
    const uint4* __restrict__ qp, const uint4* __restrict__ kp,
    const float* __restrict__ wv_g, float* __restrict__ scores)
{
    extern __shared__ char smraw[];
    ScoreSmem* sm = (ScoreSmem*)smraw;

    const int tid  = threadIdx.x;
    const int lane = tid & 31;
    const int w    = tid >> 5;

    if (tid < 32) {
        float4 f0 = *(const float4*)&wv_g[tid * 8];
        float4 f1 = *(const float4*)&wv_g[tid * 8 + 4];
        __half2 h0 = __floats2half2_rn(f0.x, f0.y);
        __half2 h1 = __floats2half2_rn(f0.z, f0.w);
        __half2 h2 = __floats2half2_rn(f1.x, f1.y);
        __half2 h3 = __floats2half2_rn(f1.z, f1.w);
        uint4 u;
        u.x = *(unsigned*)&h0; u.y = *(unsigned*)&h1;
        u.z = *(unsigned*)&h2; u.w = *(unsigned*)&h3;
        sm->wvh[tid] = u;
    }

    const int qg   = w >> 1;
    const int rowk = (w & 1) * 32 + lane;
    const int q0   = qg * 2;

    int u = blockIdx.x;
    score_prefetch(sm, qp, kp, u, 0, tid);
    cp_commit();
    int p = 0;

    while (u < NUNITS) {
        int un = u + SGRID;
        if (un < NUNITS) {
            score_prefetch(sm, qp, kp, un, p ^ 1, tid);
            cp_commit();
            asm volatile("cp.async.wait_group 1;\n");
        } else {
            asm volatile("cp.async.wait_group 0;\n");
        }
        __syncthreads();

        const uint4* kb = sm->kbh[p];
        const uint4* qs = sm->qsh[p];
        float a00 = 0.f, a01 = 0.f, a10 = 0.f, a11 = 0.f;
#pragma unroll 4
        for (int h16 = 0; h16 < 16; h16++) {
            const int hA = 2 * h16, hB = 2 * h16 + 1;
            uint4 kuA = kb[rowk * 32 + (hA ^ lane)];
            uint4 kuB = kb[rowk * 32 + (hB ^ lane)];
            uint4 quA0 = qs[q0 * 32 + hA];
            uint4 quB0 = qs[q0 * 32 + hB];
            uint4 quA1 = qs[q0 * 32 + 32 + hA];
            uint4 quB1 = qs[q0 * 32 + 32 + hB];
            uint4 wuA = sm->wvh[hA];
            uint4 wuB = sm->wvh[hB];
            __half2 kA0 = u2h(kuA.x), kA1 = u2h(kuA.y), kA2 = u2h(kuA.z), kA3 = u2h(kuA.w);
            __half2 kB0 = u2h(kuB.x), kB1 = u2h(kuB.y), kB2 = u2h(kuB.z), kB3 = u2h(kuB.w);
            __half2 wA0 = u2h(wuA.x), wA1 = u2h(wuA.y), wA2 = u2h(wuA.z), wA3 = u2h(wuA.w);
            __half2 wB0 = u2h(wuB.x), wB1 = u2h(wuB.y), wB2 = u2h(wuB.z), wB3 = u2h(wuB.w);
            __half2 s0;
            s0 = __hmul2(tanh2_ap(__hadd2(u2h(quA0.x), kA0)), wA0);
            s0 = __hfma2(tanh2_ap(__hadd2(u2h(quA0.y), kA1)), wA1, s0);
            s0 = __hfma2(tanh2_ap(__hadd2(u2h(quA0.z), kA2)), wA2, s0);
            s0 = __hfma2(tanh2_ap(__hadd2(u2h(quA0.w), kA3)), wA3, s0);
            s0 = __hfma2(tanh2_ap(__hadd2(u2h(quB0.x), kB0)), wB0, s0);
            s0 = __hfma2(tanh2_ap(__hadd2(u2h(quB0.y), kB1)), wB1, s0);
            s0 = __hfma2(tanh2_ap(__hadd2(u2h(quB0.z), kB2)), wB2, s0);
            s0 = __hfma2(tanh2_ap(__hadd2(u2h(quB0.w), kB3)), wB3, s0);
            float2 f0 = __half22float2(s0);
            a00 += f0.x; a01 += f0.y;
            __half2 s1;
            s1 = __hmul2(tanh2_ap(__hadd2(u2h(quA1.x), kA0)), wA0);
            s1 = __hfma2(tanh2_ap(__hadd2(u2h(quA1.y), kA1)), wA1, s1);
            s1 = __hfma2(tanh2_ap(__hadd2(u2h(quA1.z), kA2)), wA2, s1);
            s1 = __hfma2(tanh2_ap(__hadd2(u2h(quA1.w), kA3)), wA3, s1);
            s1 = __hfma2(tanh2_ap(__hadd2(u2h(quB1.x), kB0)), wB0, s1);
            s1 = __hfma2(tanh2_ap(__hadd2(u2h(quB1.y), kB1)), wB1, s1);
            s1 = __hfma2(tanh2_ap(__hadd2(u2h(quB1.z), kB2)), wB2, s1);
            s1 = __hfma2(tanh2_ap(__hadd2(u2h(quB1.w), kB3)), wB3, s1);
            float2 f1 = __half22float2(s1);
            a10 += f1.x; a11 += f1.y;
        }
        {
            const int qt = u >> 3;
            const int kt = u & 7;
            const int b = qt >> 6;
            const int qbase = (qt & 63) * 8;
            const int key = kt * 64 + rowk;
            scores[(size_t)(b * Qv + qbase + q0) * Kv + key]     = a00 + a01;
            scores[(size_t)(b * Qv + qbase + q0 + 1) * Kv + key] = a10 + a11;
        }
        __syncthreads();
        u = un; p ^= 1;
    }
}

// ---------------------------------------------------------------------------
// Softmax + PV via HMMA, barrier-free mainloop.
// Block = 16 queries, 256 threads (8 warps), grid 128.
// Softmax: warp w -> queries 2w, 2w+1; probs split hi/lo f16 into smem.
// PV: warp w owns dims [32w, 32w+32) -> warp-PRIVATE double-buffered V tiles
// (32 dims x 64 keys, stride 72 halves = conflict-free), cp.async per warp,
// NO __syncthreads in the 8-iteration mainloop.
// smem: Phi 16.25KB | Plo 16.25KB | Vw[8][2][32*72] 72KB = 104.5KB
// ---------------------------------------------------------------------------
#define PQ 16
#define PPS 520          // P row stride (halves)
#define VWS 72           // warp V tile row stride (halves) = 144B

struct PvSmem {
    __half Phi[PQ * PPS];
    __half Plo[PQ * PPS];
    __half Vw[8][2][32 * VWS];
};

// warp-scope: load 32 dims x 64 keys of V^T into this warp's buffer
__device__ __forceinline__ void pv_vtile_w(
    __half* dst, const uint4* vt, int b, int warpN, int kt, int lane)
{
#pragma unroll
    for (int j = 0; j < 8; j++) {
        int idx = j * 32 + lane;
        int d = idx >> 3, c = idx & 7;     // d 0..31, c 0..7 (8 uint4 = 64 keys)
        cp_async16(&dst[d * VWS + c * 8],
                   &vt[(size_t)(b * Hv + warpN + d) * 64 + kt * 8 + c]);
    }
    cp_commit();
}

__global__ __launch_bounds__(256) void softmax_pv_kernel(
    const float* __restrict__ scores, const uint4* __restrict__ vt,
    float* __restrict__ out)
{
    extern __shared__ char smraw[];
    PvSmem* sm = (PvSmem*)smraw;

    const int tid  = threadIdx.x;
    const int lane = tid & 31;
    const int w    = tid >> 5;
    const int b     = blockIdx.x >> 5;
    const int qbase = (blockIdx.x & 31) * PQ;
    const int warpN = w * 32;

    // prefetch this warp's V tile 0 (overlaps softmax)
    pv_vtile_w(sm->Vw[w][0], vt, b, warpN, 0, lane);

    // ---- softmax: warp w -> queries 2w, 2w+1 ----
    const float LOG2E = 1.4426950408889634f;
#pragma unroll
    for (int qq = 0; qq < 2; qq++) {
        const int q = 2 * w + qq;
        const float* src = &scores[(size_t)(b * Qv + qbase + q) * Kv];
        float4 xv[4];
        float mx = -1e30f;
#pragma unroll
        for (int j = 0; j < 4; j++) {
            xv[j] = *(const float4*)&src[j * 128 + lane * 4];
            mx = fmaxf(mx, fmaxf(fmaxf(xv[j].x, xv[j].y), fmaxf(xv[j].z, xv[j].w)));
        }
#pragma unroll
        for (int off = 16; off > 0; off >>= 1)
            mx = fmaxf(mx, __shfl_xor_sync(0xffffffffu, mx, off));
        float s = 0.f;
#pragma unroll
        for (int j = 0; j < 4; j++) {
            xv[j].x = ex2_ap((xv[j].x - mx) * LOG2E);
            xv[j].y = ex2_ap((xv[j].y - mx) * LOG2E);
            xv[j].z = ex2_ap((xv[j].z - mx) * LOG2E);
            xv[j].w = ex2_ap((xv[j].w - mx) * LOG2E);
            s += xv[j].x + xv[j].y + xv[j].z + xv[j].w;
        }
#pragma unroll
        for (int off = 16; off > 0; off >>= 1)
            s += __shfl_xor_sync(0xffffffffu, s, off);
        float inv = __fdividef(1.f, s);
#pragma unroll
        for (int j = 0; j < 4; j++) {
            float pv4[4] = {xv[j].x * inv, xv[j].y * inv, xv[j].z * inv, xv[j].w * inv};
            __half hi[4]; __half lo[4];
#pragma unroll
            for (int i = 0; i < 4; i++) {
                hi[i] = __float2half_rn(pv4[i]);
                lo[i] = __float2half_rn(pv4[i] - __half2float(hi[i]));
            }
            const int off4 = q * PPS + j * 128 + lane * 4;
            *(uint2*)&sm->Phi[off4] = *(uint2*)hi;
            *(uint2*)&sm->Plo[off4] = *(uint2*)lo;
        }
    }
    __syncthreads();   // P visible to all warps; only barrier before the end

    // ---- PV MMA mainloop: 8 tiles of 64 keys, warp-private, barrier-free ----
    const int kcol = (lane & 3) * 2;
    const int r0   = lane >> 2;

    float acc[4][4];
#pragma unroll
    for (int nb = 0; nb < 4; nb++)
#pragma unroll
        for (int v = 0; v < 4; v++) acc[nb][v] = 0.f;

    int p = 0;
#pragma unroll 1
    for (int kt = 0; kt < 8; kt++) {
        if (kt < 7) {
            pv_vtile_w(sm->Vw[w][p ^ 1], vt, b, warpN, kt + 1, lane);
            asm volatile("cp.async.wait_group 1;\n");
        } else {
            asm volatile("cp.async.wait_group 0;\n");
        }
        __syncwarp();

        const __half* vts = sm->Vw[w][p];
#pragma unroll
        for (int ks = 0; ks < 4; ks++) {
            const int ka = kt * 64 + ks * 16 + kcol;   // P column
            unsigned ah[4], al[4];
            ah[0] = *(const unsigned*)&sm->Phi[(r0    ) * PPS + ka];
            ah[1] = *(const unsigned*)&sm->Phi[(r0 + 8) * PPS + ka];
            ah[2] = *(const unsigned*)&sm->Phi[(r0    ) * PPS + ka + 8];
            ah[3] = *(const unsigned*)&sm->Phi[(r0 + 8) * PPS + ka + 8];
            al[0] = *(const unsigned*)&sm->Plo[(r0    ) * PPS + ka];
            al[1] = *(const unsigned*)&sm->Plo[(r0 + 8) * PPS + ka];
            al[2] = *(const unsigned*)&sm->Plo[(r0    ) * PPS + ka + 8];
            al[3] = *(const unsigned*)&sm->Plo[(r0 + 8) * PPS + ka + 8];
            const int kb = ks * 16 + kcol;             // V tile column
#pragma unroll
            for (int nb = 0; nb < 4; nb++) {
                const int n0 = nb * 8 + r0;            // local dim in warp's 32
                unsigned bh[2];
                bh[0] = *(const unsigned*)&vts[n0 * VWS + kb];
                bh[1] = *(const unsigned*)&vts[n0 * VWS + kb + 8];
                mma16816(acc[nb], ah, bh);
                mma16816(acc[nb], al, bh);
            }
        }
        p ^= 1;
    }

    // ---- store ----
    const int col = warpN + (lane & 3) * 2;
#pragma unroll
    for (int nb = 0; nb < 4; nb++) {
        size_t base0 = (size_t)(b * Qv + qbase + r0) * Hv + col + nb * 8;
        size_t base1 = (size_t)(b * Qv + qbase + r0 + 8) * Hv + col + nb * 8;
        *(float2*)&out[base0] = make_float2(acc[nb][0], acc[nb][1]);
        *(float2*)&out[base1] = make_float2(acc[nb][2], acc[nb][3]);
    }
}

extern "C" void kernel_launch(void* const* d_in, const int* in_sizes, int n_in,
                              void* d_out, int out_size)
{
    const float* queries = (const float*)d_in[0];
    const float* keys    = (const float*)d_in[1];
    const float* values  = (const float*)d_in[2];
    const float* W_q     = (const float*)d_in[3];
    const float* W_k     = (const float*)d_in[4];
    const float* w_v     = (const float*)d_in[5];
    float* out = (float*)d_out;

    uint4 *qph, *kph, *vtp; float* sc;
    cudaGetSymbolAddress((void**)&qph, g_qph);
    cudaGetSymbolAddress((void**)&kph, g_kph);
    cudaGetSymbolAddress((void**)&vtp, g_vt);
    cudaGetSymbolAddress((void**)&sc, g_sc);

    const int smP = (int)sizeof(ProjSmem);
    cudaFuncSetAttribute(proj_kernel, cudaFuncAttributeMaxDynamicSharedMemorySize, smP);
    proj_kernel<<<dim3(4, 32, 2), 128, smP>>>(queries, W_q, (__half*)qph,
                                              keys, W_k, (__half*)kph);

    vtrans_kernel<<<128, 256>>>((const float4*)values, vtp);

    const int smA = (int)sizeof(ScoreSmem);
    cudaFuncSetAttribute(score_kernel, cudaFuncAttributeMaxDynamicSharedMemorySize, smA);
    score_kernel<<<SGRID, 256, smA>>>(qph, kph, w_v, sc);

    const int smB = (int)sizeof(PvSmem);
    cudaFuncSetAttribute(softmax_pv_kernel, cudaFuncAttributeMaxDynamicSharedMemorySize, smB);
    softmax_pv_kernel<<<128, 256, smB>>>(sc, vtp, out);
}